// round 8
// baseline (speedup 1.0000x reference)
#include <cuda_runtime.h>

#define KD 512
#define QD 256
#define N_ROWS 262144

#define MAIN_BLOCKS 444
#define MAIN_THREADS 256
#define WARPS_PER_BLOCK (MAIN_THREADS / 32)
#define CHUNK 16
#define NPART MAIN_BLOCKS                       // 444 block partials
#define QBLOCKS 64                              // blocks that produce q (64*8 warps = 512 rows)
#define RBLOCKS 74
#define PART_PER_RBLOCK (NPART / RBLOCKS)       // 6

// Scratch (static __device__ — zero-initialized at module load; reset at end of each graph exec)
__device__ __align__(16) float g_q[KD];
__device__ float g_pm[NPART];
__device__ float g_pl[NPART];
__device__ __align__(16) float g_pacc[(size_t)NPART * KD];  // 0.91 MB
__device__ float g_coef[NPART];
__device__ float g_L;
__device__ __align__(16) float g_red[RBLOCKS * KD];
__device__ unsigned g_row_ctr;
__device__ unsigned g_done_a;
__device__ unsigned g_done_r;
__device__ unsigned g_qdone;
__device__ unsigned g_qflag;

__device__ __forceinline__ float neg_inf() { return __int_as_float(0xff800000); }

// safe exp(a - b): returns 0 when a == -inf (avoids -inf - -inf = NaN)
__device__ __forceinline__ float expw(float a, float b) {
    return (a == neg_inf()) ? 0.f : __expf(a - b);
}

// ---------------- Kernel 1: persistent fused kernel (qproj prologue + stream + ml-reduce) ----------------
__global__ __launch_bounds__(MAIN_THREADS, 3)
void attn_main(const float* __restrict__ query,
               const float* __restrict__ key, const float* __restrict__ value,
               const float* __restrict__ W, const float* __restrict__ b) {
    __shared__ float s_m[WARPS_PER_BLOCK];
    __shared__ float s_l[WARPS_PER_BLOCK];
    __shared__ __align__(16) float s_acc[WARPS_PER_BLOCK][KD];   // 16 KB
    __shared__ float s_red[MAIN_THREADS];
    __shared__ int s_last;

    const int lane = threadIdx.x & 31;
    const int wid  = threadIdx.x >> 5;
    const int tid  = threadIdx.x;

    // ---- prologue: blocks 0..63 compute q = W @ query + b (one row per warp) ----
    if (blockIdx.x < QBLOCKS) {
        s_red[tid] = query[tid];          // QD == MAIN_THREADS
        __syncthreads();
        const int row = blockIdx.x * WARPS_PER_BLOCK + wid;
        const float4* w4 = reinterpret_cast<const float4*>(W + (size_t)row * QD);
        const float4 wa = __ldg(&w4[lane]);
        const float4 wb = __ldg(&w4[lane + 32]);
        const int c0 = 4 * lane;
        float s = wa.x * s_red[c0] + wa.y * s_red[c0 + 1]
                + wa.z * s_red[c0 + 2] + wa.w * s_red[c0 + 3]
                + wb.x * s_red[128 + c0] + wb.y * s_red[128 + c0 + 1]
                + wb.z * s_red[128 + c0 + 2] + wb.w * s_red[128 + c0 + 3];
        #pragma unroll
        for (int o = 16; o > 0; o >>= 1) s += __shfl_xor_sync(0xffffffffu, s, o);
        if (lane == 0) g_q[row] = s + b[row];
        __syncthreads();                  // all 8 rows of this block written
        if (tid == 0) {
            __threadfence();
            const unsigned d = atomicAdd(&g_qdone, 1u);
            if (d == QBLOCKS - 1u) atomicExch(&g_qflag, 1u);   // release
        }
    }

    // ---- all blocks wait for q ----
    if (tid == 0) {
        while (__ldcg((const unsigned*)&g_qflag) == 0u) __nanosleep(32);
    }
    __syncthreads();
    __threadfence();   // acquire

    const float4* q4 = reinterpret_cast<const float4*>(g_q);
    const float4 q0 = __ldcg(&q4[lane]);
    const float4 q1 = __ldcg(&q4[lane + 32]);
    const float4 q2 = __ldcg(&q4[lane + 64]);
    const float4 q3 = __ldcg(&q4[lane + 96]);

    const float4* __restrict__ k4 = reinterpret_cast<const float4*>(key);
    const float4* __restrict__ v4 = reinterpret_cast<const float4*>(value);

    float4 a0 = make_float4(0.f, 0.f, 0.f, 0.f), a1 = a0, a2 = a0, a3 = a0;
    float m = neg_inf();
    float l = 0.f;

    // dynamic chunk grabbing with one-chunk lookahead
    unsigned cur = 0u;
    if (lane == 0) cur = atomicAdd(&g_row_ctr, (unsigned)CHUNK);
    cur = __shfl_sync(0xffffffffu, cur, 0);

    while (cur < (unsigned)N_ROWS) {
        unsigned nxt = 0u;
        if (lane == 0) nxt = atomicAdd(&g_row_ctr, (unsigned)CHUNK);  // issued early, latency hidden
        nxt = __shfl_sync(0xffffffffu, nxt, 0);

        const unsigned row_end = min(cur + (unsigned)CHUNK, (unsigned)N_ROWS);
        for (unsigned row = cur; row < row_end; ++row) {
            const size_t base = (size_t)row * (KD / 4) + lane;
            const float4 k0 = __ldcs(&k4[base]);
            const float4 k1 = __ldcs(&k4[base + 32]);
            const float4 k2 = __ldcs(&k4[base + 64]);
            const float4 k3 = __ldcs(&k4[base + 96]);
            const float4 v0 = __ldcs(&v4[base]);
            const float4 v1 = __ldcs(&v4[base + 32]);
            const float4 v2 = __ldcs(&v4[base + 64]);
            const float4 v3 = __ldcs(&v4[base + 96]);

            float s;
            s  = k0.x * q0.x + k0.y * q0.y + k0.z * q0.z + k0.w * q0.w;
            s += k1.x * q1.x + k1.y * q1.y + k1.z * q1.z + k1.w * q1.w;
            s += k2.x * q2.x + k2.y * q2.y + k2.z * q2.z + k2.w * q2.w;
            s += k3.x * q3.x + k3.y * q3.y + k3.z * q3.z + k3.w * q3.w;
            #pragma unroll
            for (int o = 16; o > 0; o >>= 1) s += __shfl_xor_sync(0xffffffffu, s, o);

            if (s > m) {
                const float sc = (m == neg_inf()) ? 0.f : __expf(m - s);
                m = s;
                l = l * sc + 1.f;
                a0.x = a0.x * sc + v0.x;  a0.y = a0.y * sc + v0.y;
                a0.z = a0.z * sc + v0.z;  a0.w = a0.w * sc + v0.w;
                a1.x = a1.x * sc + v1.x;  a1.y = a1.y * sc + v1.y;
                a1.z = a1.z * sc + v1.z;  a1.w = a1.w * sc + v1.w;
                a2.x = a2.x * sc + v2.x;  a2.y = a2.y * sc + v2.y;
                a2.z = a2.z * sc + v2.z;  a2.w = a2.w * sc + v2.w;
                a3.x = a3.x * sc + v3.x;  a3.y = a3.y * sc + v3.y;
                a3.z = a3.z * sc + v3.z;  a3.w = a3.w * sc + v3.w;
            } else {
                const float w = __expf(s - m);
                l += w;
                a0.x += w * v0.x;  a0.y += w * v0.y;  a0.z += w * v0.z;  a0.w += w * v0.w;
                a1.x += w * v1.x;  a1.y += w * v1.y;  a1.z += w * v1.z;  a1.w += w * v1.w;
                a2.x += w * v2.x;  a2.y += w * v2.y;  a2.z += w * v2.z;  a2.w += w * v2.w;
                a3.x += w * v3.x;  a3.y += w * v3.y;  a3.z += w * v3.z;  a3.w += w * v3.w;
            }
        }
        cur = nxt;
    }

    // ---- block-level reduce of 8 warp partials ----
    float4* sa = reinterpret_cast<float4*>(s_acc[wid]);
    sa[lane] = a0; sa[lane + 32] = a1; sa[lane + 64] = a2; sa[lane + 96] = a3;
    if (lane == 0) { s_m[wid] = m; s_l[wid] = l; }
    __syncthreads();

    float Mb = neg_inf();
    #pragma unroll
    for (int w = 0; w < WARPS_PER_BLOCK; ++w) Mb = fmaxf(Mb, s_m[w]);
    float c[WARPS_PER_BLOCK];
    #pragma unroll
    for (int w = 0; w < WARPS_PER_BLOCK; ++w) c[w] = expw(s_m[w], Mb);

    #pragma unroll
    for (int r = 0; r < 2; ++r) {
        const int d = tid + r * MAIN_THREADS;
        float acc = 0.f;
        #pragma unroll
        for (int w = 0; w < WARPS_PER_BLOCK; ++w) acc += c[w] * s_acc[w][d];
        g_pacc[(size_t)blockIdx.x * KD + d] = acc;
    }
    if (tid == 0) {
        float lb = 0.f;
        #pragma unroll
        for (int w = 0; w < WARPS_PER_BLOCK; ++w) lb += c[w] * s_l[w];
        g_pm[blockIdx.x] = Mb;
        g_pl[blockIdx.x] = lb;
    }
    __syncthreads();

    // ---- last finishing block computes global max, coefs, L ----
    if (tid == 0) {
        __threadfence();
        const unsigned d = atomicAdd(&g_done_a, 1u);
        s_last = (d == MAIN_BLOCKS - 1u) ? 1 : 0;
    }
    __syncthreads();
    if (!s_last) return;

    float mx = neg_inf();
    for (int i = tid; i < NPART; i += MAIN_THREADS) mx = fmaxf(mx, __ldcg(&g_pm[i]));
    s_red[tid] = mx;
    __syncthreads();
    #pragma unroll
    for (int o = MAIN_THREADS / 2; o > 0; o >>= 1) {
        if (tid < o) s_red[tid] = fmaxf(s_red[tid], s_red[tid + o]);
        __syncthreads();
    }
    const float M = s_red[0];
    __syncthreads();

    float ls = 0.f;
    for (int i = tid; i < NPART; i += MAIN_THREADS) {
        const float pm = __ldcg(&g_pm[i]);
        const float cc = expw(pm, M);
        g_coef[i] = cc;
        ls += cc * __ldcg(&g_pl[i]);
    }
    s_red[tid] = ls;
    __syncthreads();
    #pragma unroll
    for (int o = MAIN_THREADS / 2; o > 0; o >>= 1) {
        if (tid < o) s_red[tid] += s_red[tid + o];
        __syncthreads();
    }
    if (tid == 0) g_L = s_red[0];
}

// ---------------- Kernel 2: weighted reduce + fused finalize + counter reset ----------------
__global__ void reduce_out(float* __restrict__ out) {
    __shared__ int s_last;
    const int t = threadIdx.x;                 // 512 threads, one dim each
    const int b0 = blockIdx.x * PART_PER_RBLOCK;
    float acc = 0.f;
    #pragma unroll
    for (int b = b0; b < b0 + PART_PER_RBLOCK; ++b)
        acc += g_coef[b] * g_pacc[(size_t)b * KD + t];
    g_red[blockIdx.x * KD + t] = acc;
    __syncthreads();

    if (t == 0) {
        __threadfence();
        const unsigned d = atomicAdd(&g_done_r, 1u);
        s_last = (d == RBLOCKS - 1u) ? 1 : 0;
    }
    __syncthreads();
    if (!s_last) return;

    float a = 0.f;
    #pragma unroll
    for (int p = 0; p < RBLOCKS; ++p) a += __ldcg(&g_red[p * KD + t]);
    out[t] = a / g_L;

    // reset counters for the next graph replay (first call relies on zero-init)
    if (t == 0) {
        g_row_ctr = 0u; g_done_a = 0u; g_done_r = 0u;
        g_qdone = 0u; g_qflag = 0u;
        __threadfence();
    }
}

extern "C" void kernel_launch(void* const* d_in, const int* in_sizes, int n_in,
                              void* d_out, int out_size) {
    const float* query = (const float*)d_in[0];
    const float* key   = (const float*)d_in[1];
    const float* value = (const float*)d_in[2];
    const float* W     = (const float*)d_in[3];
    const float* b     = (const float*)d_in[4];
    float* out = (float*)d_out;

    attn_main<<<MAIN_BLOCKS, MAIN_THREADS>>>(query, key, value, W, b);
    reduce_out<<<RBLOCKS, KD>>>(out);
}

// round 9
// speedup vs baseline: 1.0006x; 1.0006x over previous
#include <cuda_runtime.h>

#define KD 512
#define QD 256
#define N_ROWS 262144

#define MAIN_BLOCKS 444
#define MAIN_THREADS 256
#define WARPS_PER_BLOCK (MAIN_THREADS / 32)
#define CHUNK 32
#define NPART MAIN_BLOCKS                       // 444 block partials
#define RBLOCKS 37
#define PART_PER_RBLOCK (NPART / RBLOCKS)       // 12

// Scratch (static __device__ — no allocations allowed)
__device__ __align__(16) float g_q[KD];
__device__ float g_pm[NPART];
__device__ float g_pl[NPART];
__device__ __align__(16) float g_pacc[(size_t)NPART * KD];  // 0.91 MB
__device__ float g_coef[NPART];
__device__ float g_L;
__device__ __align__(16) float g_red[RBLOCKS * KD];
__device__ unsigned g_row_ctr;
__device__ unsigned g_done_a;
__device__ unsigned g_done_r;

__device__ __forceinline__ float neg_inf() { return __int_as_float(0xff800000); }

// safe exp(a - b): returns 0 when a == -inf (avoids -inf - -inf = NaN)
__device__ __forceinline__ float expw(float a, float b) {
    return (a == neg_inf()) ? 0.f : __expf(a - b);
}

// ---------------- Kernel 1: q = W @ query + b (64 blocks) + counter reset ----------------
__global__ void qproj_kernel(const float* __restrict__ query,
                             const float* __restrict__ W,
                             const float* __restrict__ b) {
    if (blockIdx.x == 0 && threadIdx.x == 0) {
        g_row_ctr = 0u; g_done_a = 0u; g_done_r = 0u;
    }
    __shared__ float sq[QD];
    sq[threadIdx.x] = query[threadIdx.x];
    __syncthreads();
    const int wid = threadIdx.x >> 5;
    const int lane = threadIdx.x & 31;
    const int row = blockIdx.x * WARPS_PER_BLOCK + wid;   // 64*8 = 512 rows
    const float4* w4 = reinterpret_cast<const float4*>(W + (size_t)row * QD);
    const float4 wa = w4[lane];
    const float4 wb = w4[lane + 32];
    const int c0 = 4 * lane;
    float s = wa.x * sq[c0] + wa.y * sq[c0 + 1] + wa.z * sq[c0 + 2] + wa.w * sq[c0 + 3]
            + wb.x * sq[128 + c0] + wb.y * sq[128 + c0 + 1]
            + wb.z * sq[128 + c0 + 2] + wb.w * sq[128 + c0 + 3];
    #pragma unroll
    for (int o = 16; o > 0; o >>= 1) s += __shfl_xor_sync(0xffffffffu, s, o);
    if (lane == 0) g_q[row] = s + b[row];
}

// ---------------- Kernel 2: fused streaming pass, dynamic chunks, fused ml-reduce ----------------
__global__ __launch_bounds__(MAIN_THREADS, 3)
void attn_main(const float* __restrict__ key, const float* __restrict__ value) {
    __shared__ float s_m[WARPS_PER_BLOCK];
    __shared__ float s_l[WARPS_PER_BLOCK];
    __shared__ __align__(16) float s_acc[WARPS_PER_BLOCK][KD];   // 16 KB
    __shared__ float s_red[MAIN_THREADS];
    __shared__ int s_last;

    const int lane = threadIdx.x & 31;
    const int wid  = threadIdx.x >> 5;
    const int tid  = threadIdx.x;

    const float4* q4 = reinterpret_cast<const float4*>(g_q);
    const float4 q0 = q4[lane], q1 = q4[lane + 32], q2 = q4[lane + 64], q3 = q4[lane + 96];

    const float4* __restrict__ k4 = reinterpret_cast<const float4*>(key);
    const float4* __restrict__ v4 = reinterpret_cast<const float4*>(value);

    float4 a0 = make_float4(0.f, 0.f, 0.f, 0.f), a1 = a0, a2 = a0, a3 = a0;
    float m = neg_inf();
    float l = 0.f;

    // dynamic chunk grabbing with one-chunk lookahead
    unsigned cur = 0u;
    if (lane == 0) cur = atomicAdd(&g_row_ctr, (unsigned)CHUNK);
    cur = __shfl_sync(0xffffffffu, cur, 0);

    while (cur < (unsigned)N_ROWS) {
        unsigned nxt = 0u;
        if (lane == 0) nxt = atomicAdd(&g_row_ctr, (unsigned)CHUNK);  // issued early, latency hidden
        nxt = __shfl_sync(0xffffffffu, nxt, 0);

        const unsigned row_end = min(cur + (unsigned)CHUNK, (unsigned)N_ROWS);
        for (unsigned row = cur; row < row_end; ++row) {
            const size_t base = (size_t)row * (KD / 4) + lane;
            const float4 k0 = __ldcs(&k4[base]);
            const float4 k1 = __ldcs(&k4[base + 32]);
            const float4 k2 = __ldcs(&k4[base + 64]);
            const float4 k3 = __ldcs(&k4[base + 96]);
            const float4 v0 = __ldcs(&v4[base]);
            const float4 v1 = __ldcs(&v4[base + 32]);
            const float4 v2 = __ldcs(&v4[base + 64]);
            const float4 v3 = __ldcs(&v4[base + 96]);

            float s;
            s  = k0.x * q0.x + k0.y * q0.y + k0.z * q0.z + k0.w * q0.w;
            s += k1.x * q1.x + k1.y * q1.y + k1.z * q1.z + k1.w * q1.w;
            s += k2.x * q2.x + k2.y * q2.y + k2.z * q2.z + k2.w * q2.w;
            s += k3.x * q3.x + k3.y * q3.y + k3.z * q3.z + k3.w * q3.w;
            #pragma unroll
            for (int o = 16; o > 0; o >>= 1) s += __shfl_xor_sync(0xffffffffu, s, o);

            if (s > m) {
                const float sc = (m == neg_inf()) ? 0.f : __expf(m - s);
                m = s;
                l = l * sc + 1.f;
                a0.x = a0.x * sc + v0.x;  a0.y = a0.y * sc + v0.y;
                a0.z = a0.z * sc + v0.z;  a0.w = a0.w * sc + v0.w;
                a1.x = a1.x * sc + v1.x;  a1.y = a1.y * sc + v1.y;
                a1.z = a1.z * sc + v1.z;  a1.w = a1.w * sc + v1.w;
                a2.x = a2.x * sc + v2.x;  a2.y = a2.y * sc + v2.y;
                a2.z = a2.z * sc + v2.z;  a2.w = a2.w * sc + v2.w;
                a3.x = a3.x * sc + v3.x;  a3.y = a3.y * sc + v3.y;
                a3.z = a3.z * sc + v3.z;  a3.w = a3.w * sc + v3.w;
            } else {
                const float w = __expf(s - m);
                l += w;
                a0.x += w * v0.x;  a0.y += w * v0.y;  a0.z += w * v0.z;  a0.w += w * v0.w;
                a1.x += w * v1.x;  a1.y += w * v1.y;  a1.z += w * v1.z;  a1.w += w * v1.w;
                a2.x += w * v2.x;  a2.y += w * v2.y;  a2.z += w * v2.z;  a2.w += w * v2.w;
                a3.x += w * v3.x;  a3.y += w * v3.y;  a3.z += w * v3.z;  a3.w += w * v3.w;
            }
        }
        cur = nxt;
    }

    // ---- block-level reduce of 8 warp partials ----
    float4* sa = reinterpret_cast<float4*>(s_acc[wid]);
    sa[lane] = a0; sa[lane + 32] = a1; sa[lane + 64] = a2; sa[lane + 96] = a3;
    if (lane == 0) { s_m[wid] = m; s_l[wid] = l; }
    __syncthreads();

    float Mb = neg_inf();
    #pragma unroll
    for (int w = 0; w < WARPS_PER_BLOCK; ++w) Mb = fmaxf(Mb, s_m[w]);
    float c[WARPS_PER_BLOCK];
    #pragma unroll
    for (int w = 0; w < WARPS_PER_BLOCK; ++w) c[w] = expw(s_m[w], Mb);

    #pragma unroll
    for (int r = 0; r < 2; ++r) {
        const int d = tid + r * MAIN_THREADS;
        float acc = 0.f;
        #pragma unroll
        for (int w = 0; w < WARPS_PER_BLOCK; ++w) acc += c[w] * s_acc[w][d];
        g_pacc[(size_t)blockIdx.x * KD + d] = acc;
    }
    if (tid == 0) {
        float lb = 0.f;
        #pragma unroll
        for (int w = 0; w < WARPS_PER_BLOCK; ++w) lb += c[w] * s_l[w];
        g_pm[blockIdx.x] = Mb;
        g_pl[blockIdx.x] = lb;
    }
    __syncthreads();

    // ---- last finishing block computes global max, coefs, L ----
    if (tid == 0) {
        __threadfence();
        const unsigned d = atomicAdd(&g_done_a, 1u);
        s_last = (d == MAIN_BLOCKS - 1u) ? 1 : 0;
    }
    __syncthreads();
    if (!s_last) return;

    float mx = neg_inf();
    for (int i = tid; i < NPART; i += MAIN_THREADS) mx = fmaxf(mx, __ldcg(&g_pm[i]));
    s_red[tid] = mx;
    __syncthreads();
    #pragma unroll
    for (int o = MAIN_THREADS / 2; o > 0; o >>= 1) {
        if (tid < o) s_red[tid] = fmaxf(s_red[tid], s_red[tid + o]);
        __syncthreads();
    }
    const float M = s_red[0];
    __syncthreads();

    float ls = 0.f;
    for (int i = tid; i < NPART; i += MAIN_THREADS) {
        const float pm = __ldcg(&g_pm[i]);
        const float cc = expw(pm, M);
        g_coef[i] = cc;
        ls += cc * __ldcg(&g_pl[i]);
    }
    s_red[tid] = ls;
    __syncthreads();
    #pragma unroll
    for (int o = MAIN_THREADS / 2; o > 0; o >>= 1) {
        if (tid < o) s_red[tid] += s_red[tid + o];
        __syncthreads();
    }
    if (tid == 0) g_L = s_red[0];
}

// ---------------- Kernel 3: weighted reduce + fused finalize ----------------
__global__ void reduce_out(float* __restrict__ out) {
    __shared__ int s_last;
    const int t = threadIdx.x;                 // 512 threads, one dim each
    const int b0 = blockIdx.x * PART_PER_RBLOCK;
    float acc = 0.f;
    #pragma unroll
    for (int b = b0; b < b0 + PART_PER_RBLOCK; ++b)
        acc += g_coef[b] * g_pacc[(size_t)b * KD + t];
    g_red[blockIdx.x * KD + t] = acc;
    __syncthreads();

    if (t == 0) {
        __threadfence();
        const unsigned d = atomicAdd(&g_done_r, 1u);
        s_last = (d == RBLOCKS - 1u) ? 1 : 0;
    }
    __syncthreads();
    if (!s_last) return;

    float a = 0.f;
    #pragma unroll
    for (int p = 0; p < RBLOCKS; ++p) a += __ldcg(&g_red[p * KD + t]);
    out[t] = a / g_L;
}

extern "C" void kernel_launch(void* const* d_in, const int* in_sizes, int n_in,
                              void* d_out, int out_size) {
    const float* query = (const float*)d_in[0];
    const float* key   = (const float*)d_in[1];
    const float* value = (const float*)d_in[2];
    const float* W     = (const float*)d_in[3];
    const float* b     = (const float*)d_in[4];
    float* out = (float*)d_out;

    qproj_kernel<<<64, QD>>>(query, W, b);
    attn_main<<<MAIN_BLOCKS, MAIN_THREADS>>>(key, value);
    reduce_out<<<RBLOCKS, KD>>>(out);
}

// round 10
// speedup vs baseline: 1.0128x; 1.0122x over previous
#include <cuda_runtime.h>

#define KD 512
#define QD 256
#define N_ROWS 262144

#define MAIN_BLOCKS 444
#define MAIN_THREADS 256
#define WARPS_PER_BLOCK (MAIN_THREADS / 32)
#define CHUNK 16
#define NPART MAIN_BLOCKS                       // 444 block partials
#define RBLOCKS 37
#define PART_PER_RBLOCK (NPART / RBLOCKS)       // 12

// Scratch (static __device__ — no allocations allowed)
__device__ __align__(16) float g_q[KD];
__device__ float g_pm[NPART];
__device__ float g_pl[NPART];
__device__ __align__(16) float g_pacc[(size_t)NPART * KD];  // 0.91 MB
__device__ float g_coef[NPART];
__device__ float g_L;
__device__ __align__(16) float g_red[RBLOCKS * KD];
__device__ unsigned g_row_ctr;
__device__ unsigned g_done_a;
__device__ unsigned g_done_r;

__device__ __forceinline__ float neg_inf() { return __int_as_float(0xff800000); }

// safe exp(a - b): returns 0 when a == -inf (avoids -inf - -inf = NaN)
__device__ __forceinline__ float expw(float a, float b) {
    return (a == neg_inf()) ? 0.f : __expf(a - b);
}

// ---------------- Kernel 1: q = W @ query + b (128 blocks x 4 warps, 1 row/warp) ----------------
__global__ __launch_bounds__(128)
void qproj_kernel(const float* __restrict__ query,
                  const float* __restrict__ W,
                  const float* __restrict__ b) {
    if (blockIdx.x == 0 && threadIdx.x == 0) {
        g_row_ctr = 0u; g_done_a = 0u; g_done_r = 0u;
    }
    const int wid  = threadIdx.x >> 5;
    const int lane = threadIdx.x & 31;
    const int row  = blockIdx.x * 4 + wid;      // 128*4 = 512 rows

    const float4* w4 = reinterpret_cast<const float4*>(W + (size_t)row * QD);
    const float4* q4 = reinterpret_cast<const float4*>(query);
    const float4 wa = __ldg(&w4[lane]);
    const float4 wb = __ldg(&w4[lane + 32]);
    const float4 qa = __ldg(&q4[lane]);          // query[4*lane .. 4*lane+3]
    const float4 qb = __ldg(&q4[lane + 32]);     // query[128+4*lane ..]

    float s = wa.x * qa.x + wa.y * qa.y + wa.z * qa.z + wa.w * qa.w
            + wb.x * qb.x + wb.y * qb.y + wb.z * qb.z + wb.w * qb.w;
    #pragma unroll
    for (int o = 16; o > 0; o >>= 1) s += __shfl_xor_sync(0xffffffffu, s, o);
    if (lane == 0) g_q[row] = s + b[row];
}

// ---------------- Kernel 2: fused streaming pass, dynamic chunks, fused ml-reduce ----------------
__global__ __launch_bounds__(MAIN_THREADS, 3)
void attn_main(const float* __restrict__ key, const float* __restrict__ value) {
    __shared__ float s_m[WARPS_PER_BLOCK];
    __shared__ float s_l[WARPS_PER_BLOCK];
    __shared__ __align__(16) float s_acc[WARPS_PER_BLOCK][KD];   // 16 KB
    __shared__ float s_red[MAIN_THREADS];
    __shared__ int s_last;

    const int lane = threadIdx.x & 31;
    const int wid  = threadIdx.x >> 5;
    const int tid  = threadIdx.x;

    const float4* q4 = reinterpret_cast<const float4*>(g_q);
    const float4 q0 = q4[lane], q1 = q4[lane + 32], q2 = q4[lane + 64], q3 = q4[lane + 96];

    const float4* __restrict__ k4 = reinterpret_cast<const float4*>(key);
    const float4* __restrict__ v4 = reinterpret_cast<const float4*>(value);

    float4 a0 = make_float4(0.f, 0.f, 0.f, 0.f), a1 = a0, a2 = a0, a3 = a0;
    float m = neg_inf();
    float l = 0.f;

    // dynamic chunk grabbing with one-chunk lookahead
    unsigned cur = 0u;
    if (lane == 0) cur = atomicAdd(&g_row_ctr, (unsigned)CHUNK);
    cur = __shfl_sync(0xffffffffu, cur, 0);

    while (cur < (unsigned)N_ROWS) {
        unsigned nxt = 0u;
        if (lane == 0) nxt = atomicAdd(&g_row_ctr, (unsigned)CHUNK);  // issued early, latency hidden
        nxt = __shfl_sync(0xffffffffu, nxt, 0);

        const unsigned row_end = min(cur + (unsigned)CHUNK, (unsigned)N_ROWS);
        for (unsigned row = cur; row < row_end; ++row) {
            const size_t base = (size_t)row * (KD / 4) + lane;
            const float4 k0 = __ldcs(&k4[base]);
            const float4 k1 = __ldcs(&k4[base + 32]);
            const float4 k2 = __ldcs(&k4[base + 64]);
            const float4 k3 = __ldcs(&k4[base + 96]);
            const float4 v0 = __ldcs(&v4[base]);
            const float4 v1 = __ldcs(&v4[base + 32]);
            const float4 v2 = __ldcs(&v4[base + 64]);
            const float4 v3 = __ldcs(&v4[base + 96]);

            float s;
            s  = k0.x * q0.x + k0.y * q0.y + k0.z * q0.z + k0.w * q0.w;
            s += k1.x * q1.x + k1.y * q1.y + k1.z * q1.z + k1.w * q1.w;
            s += k2.x * q2.x + k2.y * q2.y + k2.z * q2.z + k2.w * q2.w;
            s += k3.x * q3.x + k3.y * q3.y + k3.z * q3.z + k3.w * q3.w;
            #pragma unroll
            for (int o = 16; o > 0; o >>= 1) s += __shfl_xor_sync(0xffffffffu, s, o);

            if (s > m) {
                const float sc = (m == neg_inf()) ? 0.f : __expf(m - s);
                m = s;
                l = l * sc + 1.f;
                a0.x = a0.x * sc + v0.x;  a0.y = a0.y * sc + v0.y;
                a0.z = a0.z * sc + v0.z;  a0.w = a0.w * sc + v0.w;
                a1.x = a1.x * sc + v1.x;  a1.y = a1.y * sc + v1.y;
                a1.z = a1.z * sc + v1.z;  a1.w = a1.w * sc + v1.w;
                a2.x = a2.x * sc + v2.x;  a2.y = a2.y * sc + v2.y;
                a2.z = a2.z * sc + v2.z;  a2.w = a2.w * sc + v2.w;
                a3.x = a3.x * sc + v3.x;  a3.y = a3.y * sc + v3.y;
                a3.z = a3.z * sc + v3.z;  a3.w = a3.w * sc + v3.w;
            } else {
                const float w = __expf(s - m);
                l += w;
                a0.x += w * v0.x;  a0.y += w * v0.y;  a0.z += w * v0.z;  a0.w += w * v0.w;
                a1.x += w * v1.x;  a1.y += w * v1.y;  a1.z += w * v1.z;  a1.w += w * v1.w;
                a2.x += w * v2.x;  a2.y += w * v2.y;  a2.z += w * v2.z;  a2.w += w * v2.w;
                a3.x += w * v3.x;  a3.y += w * v3.y;  a3.z += w * v3.z;  a3.w += w * v3.w;
            }
        }
        cur = nxt;
    }

    // ---- block-level reduce of 8 warp partials ----
    float4* sa = reinterpret_cast<float4*>(s_acc[wid]);
    sa[lane] = a0; sa[lane + 32] = a1; sa[lane + 64] = a2; sa[lane + 96] = a3;
    if (lane == 0) { s_m[wid] = m; s_l[wid] = l; }
    __syncthreads();

    float Mb = neg_inf();
    #pragma unroll
    for (int w = 0; w < WARPS_PER_BLOCK; ++w) Mb = fmaxf(Mb, s_m[w]);
    float c[WARPS_PER_BLOCK];
    #pragma unroll
    for (int w = 0; w < WARPS_PER_BLOCK; ++w) c[w] = expw(s_m[w], Mb);

    #pragma unroll
    for (int r = 0; r < 2; ++r) {
        const int d = tid + r * MAIN_THREADS;
        float acc = 0.f;
        #pragma unroll
        for (int w = 0; w < WARPS_PER_BLOCK; ++w) acc += c[w] * s_acc[w][d];
        g_pacc[(size_t)blockIdx.x * KD + d] = acc;
    }
    if (tid == 0) {
        float lb = 0.f;
        #pragma unroll
        for (int w = 0; w < WARPS_PER_BLOCK; ++w) lb += c[w] * s_l[w];
        g_pm[blockIdx.x] = Mb;
        g_pl[blockIdx.x] = lb;
    }
    __syncthreads();

    // ---- last finishing block computes global max, coefs, L ----
    if (tid == 0) {
        __threadfence();
        const unsigned d = atomicAdd(&g_done_a, 1u);
        s_last = (d == MAIN_BLOCKS - 1u) ? 1 : 0;
    }
    __syncthreads();
    if (!s_last) return;

    float mx = neg_inf();
    for (int i = tid; i < NPART; i += MAIN_THREADS) mx = fmaxf(mx, __ldcg(&g_pm[i]));
    s_red[tid] = mx;
    __syncthreads();
    #pragma unroll
    for (int o = MAIN_THREADS / 2; o > 0; o >>= 1) {
        if (tid < o) s_red[tid] = fmaxf(s_red[tid], s_red[tid + o]);
        __syncthreads();
    }
    const float M = s_red[0];
    __syncthreads();

    float ls = 0.f;
    for (int i = tid; i < NPART; i += MAIN_THREADS) {
        const float pm = __ldcg(&g_pm[i]);
        const float cc = expw(pm, M);
        g_coef[i] = cc;
        ls += cc * __ldcg(&g_pl[i]);
    }
    s_red[tid] = ls;
    __syncthreads();
    #pragma unroll
    for (int o = MAIN_THREADS / 2; o > 0; o >>= 1) {
        if (tid < o) s_red[tid] += s_red[tid + o];
        __syncthreads();
    }
    if (tid == 0) g_L = s_red[0];
}

// ---------------- Kernel 3: weighted reduce + fused finalize ----------------
__global__ void reduce_out(float* __restrict__ out) {
    __shared__ int s_last;
    const int t = threadIdx.x;                 // 512 threads, one dim each
    const int b0 = blockIdx.x * PART_PER_RBLOCK;
    float acc = 0.f;
    #pragma unroll
    for (int b = b0; b < b0 + PART_PER_RBLOCK; ++b)
        acc += g_coef[b] * g_pacc[(size_t)b * KD + t];
    g_red[blockIdx.x * KD + t] = acc;
    __syncthreads();

    if (t == 0) {
        __threadfence();
        const unsigned d = atomicAdd(&g_done_r, 1u);
        s_last = (d == RBLOCKS - 1u) ? 1 : 0;
    }
    __syncthreads();
    if (!s_last) return;

    float a = 0.f;
    #pragma unroll
    for (int p = 0; p < RBLOCKS; ++p) a += __ldcg(&g_red[p * KD + t]);
    out[t] = a / g_L;
}

extern "C" void kernel_launch(void* const* d_in, const int* in_sizes, int n_in,
                              void* d_out, int out_size) {
    const float* query = (const float*)d_in[0];
    const float* key   = (const float*)d_in[1];
    const float* value = (const float*)d_in[2];
    const float* W     = (const float*)d_in[3];
    const float* b     = (const float*)d_in[4];
    float* out = (float*)d_out;

    qproj_kernel<<<128, 128>>>(query, W, b);
    attn_main<<<MAIN_BLOCKS, MAIN_THREADS>>>(key, value);
    reduce_out<<<RBLOCKS, KD>>>(out);
}

// round 12
// speedup vs baseline: 1.0502x; 1.0370x over previous
#include <cuda_runtime.h>

#define KD 512
#define QD 256
#define N_ROWS 262144

#define MAIN_BLOCKS 444
#define MAIN_THREADS 256
#define WARPS_PER_BLOCK (MAIN_THREADS / 32)
#define CHUNK 16
#define NGROUPS 37
#define GROUP_SIZE (MAIN_BLOCKS / NGROUPS)      // 12

// Scratch (static __device__ — no allocations allowed)
__device__ __align__(16) float g_q[KD];
__device__ float g_pm[MAIN_BLOCKS];
__device__ float g_pl[MAIN_BLOCKS];
__device__ __align__(16) float g_pacc[(size_t)MAIN_BLOCKS * KD];  // 0.91 MB
__device__ float g_gm[NGROUPS];
__device__ float g_gl[NGROUPS];
__device__ __align__(16) float g_gacc[NGROUPS * KD];              // 76 KB
__device__ unsigned g_row_ctr;
__device__ unsigned g_gdone[NGROUPS];

__device__ __forceinline__ float neg_inf() { return __int_as_float(0xff800000); }

// safe exp(a - b): returns 0 when a == -inf (avoids -inf - -inf = NaN)
__device__ __forceinline__ float expw(float a, float b) {
    return (a == neg_inf()) ? 0.f : __expf(a - b);
}

// ---------------- Kernel 1: q = W @ query + b (128 blocks x 4 warps) + counter resets ----------------
__global__ __launch_bounds__(128)
void qproj_kernel(const float* __restrict__ query,
                  const float* __restrict__ W,
                  const float* __restrict__ b) {
    if (blockIdx.x == 0) {
        if (threadIdx.x == 0) g_row_ctr = 0u;
        if (threadIdx.x < NGROUPS) g_gdone[threadIdx.x] = 0u;
    }
    const int wid  = threadIdx.x >> 5;
    const int lane = threadIdx.x & 31;
    const int row  = blockIdx.x * 4 + wid;      // 128*4 = 512 rows

    const float4* w4 = reinterpret_cast<const float4*>(W + (size_t)row * QD);
    const float4* q4 = reinterpret_cast<const float4*>(query);
    const float4 wa = __ldg(&w4[lane]);
    const float4 wb = __ldg(&w4[lane + 32]);
    const float4 qa = __ldg(&q4[lane]);
    const float4 qb = __ldg(&q4[lane + 32]);

    float s = wa.x * qa.x + wa.y * qa.y + wa.z * qa.z + wa.w * qa.w
            + wb.x * qb.x + wb.y * qb.y + wb.z * qb.z + wb.w * qb.w;
    #pragma unroll
    for (int o = 16; o > 0; o >>= 1) s += __shfl_xor_sync(0xffffffffu, s, o);
    if (lane == 0) g_q[row] = s + b[row];
}

// ---------------- Kernel 2: streaming pass + overlapped group pre-reduce ----------------
__global__ __launch_bounds__(MAIN_THREADS, 3)
void attn_main(const float* __restrict__ key, const float* __restrict__ value) {
    __shared__ float s_m[WARPS_PER_BLOCK];
    __shared__ float s_l[WARPS_PER_BLOCK];
    __shared__ __align__(16) float s_acc[WARPS_PER_BLOCK][KD];   // 16 KB
    __shared__ int s_last;

    const int lane = threadIdx.x & 31;
    const int wid  = threadIdx.x >> 5;
    const int tid  = threadIdx.x;

    const float4* q4 = reinterpret_cast<const float4*>(g_q);
    const float4 q0 = q4[lane], q1 = q4[lane + 32], q2 = q4[lane + 64], q3 = q4[lane + 96];

    const float4* __restrict__ k4 = reinterpret_cast<const float4*>(key);
    const float4* __restrict__ v4 = reinterpret_cast<const float4*>(value);

    float4 a0 = make_float4(0.f, 0.f, 0.f, 0.f), a1 = a0, a2 = a0, a3 = a0;
    float m = neg_inf();
    float l = 0.f;

    // dynamic chunk grabbing with one-chunk lookahead
    unsigned cur = 0u;
    if (lane == 0) cur = atomicAdd(&g_row_ctr, (unsigned)CHUNK);
    cur = __shfl_sync(0xffffffffu, cur, 0);

    while (cur < (unsigned)N_ROWS) {
        unsigned nxt = 0u;
        if (lane == 0) nxt = atomicAdd(&g_row_ctr, (unsigned)CHUNK);
        nxt = __shfl_sync(0xffffffffu, nxt, 0);

        const unsigned row_end = min(cur + (unsigned)CHUNK, (unsigned)N_ROWS);
        for (unsigned row = cur; row < row_end; ++row) {
            const size_t base = (size_t)row * (KD / 4) + lane;
            const float4 k0 = __ldcs(&k4[base]);
            const float4 k1 = __ldcs(&k4[base + 32]);
            const float4 k2 = __ldcs(&k4[base + 64]);
            const float4 k3 = __ldcs(&k4[base + 96]);
            const float4 v0 = __ldcs(&v4[base]);
            const float4 v1 = __ldcs(&v4[base + 32]);
            const float4 v2 = __ldcs(&v4[base + 64]);
            const float4 v3 = __ldcs(&v4[base + 96]);

            float s;
            s  = k0.x * q0.x + k0.y * q0.y + k0.z * q0.z + k0.w * q0.w;
            s += k1.x * q1.x + k1.y * q1.y + k1.z * q1.z + k1.w * q1.w;
            s += k2.x * q2.x + k2.y * q2.y + k2.z * q2.z + k2.w * q2.w;
            s += k3.x * q3.x + k3.y * q3.y + k3.z * q3.z + k3.w * q3.w;
            #pragma unroll
            for (int o = 16; o > 0; o >>= 1) s += __shfl_xor_sync(0xffffffffu, s, o);

            if (s > m) {
                const float sc = (m == neg_inf()) ? 0.f : __expf(m - s);
                m = s;
                l = l * sc + 1.f;
                a0.x = a0.x * sc + v0.x;  a0.y = a0.y * sc + v0.y;
                a0.z = a0.z * sc + v0.z;  a0.w = a0.w * sc + v0.w;
                a1.x = a1.x * sc + v1.x;  a1.y = a1.y * sc + v1.y;
                a1.z = a1.z * sc + v1.z;  a1.w = a1.w * sc + v1.w;
                a2.x = a2.x * sc + v2.x;  a2.y = a2.y * sc + v2.y;
                a2.z = a2.z * sc + v2.z;  a2.w = a2.w * sc + v2.w;
                a3.x = a3.x * sc + v3.x;  a3.y = a3.y * sc + v3.y;
                a3.z = a3.z * sc + v3.z;  a3.w = a3.w * sc + v3.w;
            } else {
                const float w = __expf(s - m);
                l += w;
                a0.x += w * v0.x;  a0.y += w * v0.y;  a0.z += w * v0.z;  a0.w += w * v0.w;
                a1.x += w * v1.x;  a1.y += w * v1.y;  a1.z += w * v1.z;  a1.w += w * v1.w;
                a2.x += w * v2.x;  a2.y += w * v2.y;  a2.z += w * v2.z;  a2.w += w * v2.w;
                a3.x += w * v3.x;  a3.y += w * v3.y;  a3.z += w * v3.z;  a3.w += w * v3.w;
            }
        }
        cur = nxt;
    }

    // ---- block-level reduce of 8 warp partials ----
    float4* sa = reinterpret_cast<float4*>(s_acc[wid]);
    sa[lane] = a0; sa[lane + 32] = a1; sa[lane + 64] = a2; sa[lane + 96] = a3;
    if (lane == 0) { s_m[wid] = m; s_l[wid] = l; }
    __syncthreads();

    float Mb = neg_inf();
    #pragma unroll
    for (int w = 0; w < WARPS_PER_BLOCK; ++w) Mb = fmaxf(Mb, s_m[w]);
    float c[WARPS_PER_BLOCK];
    #pragma unroll
    for (int w = 0; w < WARPS_PER_BLOCK; ++w) c[w] = expw(s_m[w], Mb);

    #pragma unroll
    for (int r = 0; r < 2; ++r) {
        const int d = tid + r * MAIN_THREADS;
        float acc = 0.f;
        #pragma unroll
        for (int w = 0; w < WARPS_PER_BLOCK; ++w) acc += c[w] * s_acc[w][d];
        g_pacc[(size_t)blockIdx.x * KD + d] = acc;
    }
    if (tid == 0) {
        float lb = 0.f;
        #pragma unroll
        for (int w = 0; w < WARPS_PER_BLOCK; ++w) lb += c[w] * s_l[w];
        g_pm[blockIdx.x] = Mb;
        g_pl[blockIdx.x] = lb;
    }
    __syncthreads();

    // ---- group ticket: last finisher of each 12-block group pre-reduces (overlaps stream) ----
    const int grp = blockIdx.x / GROUP_SIZE;
    if (tid == 0) {
        __threadfence();
        const unsigned d = atomicAdd(&g_gdone[grp], 1u);
        s_last = (d == GROUP_SIZE - 1u) ? 1 : 0;
    }
    __syncthreads();
    if (!s_last) return;

    const int b0 = grp * GROUP_SIZE;
    float gm = neg_inf();
    #pragma unroll
    for (int bb = 0; bb < GROUP_SIZE; ++bb) gm = fmaxf(gm, __ldcg(&g_pm[b0 + bb]));
    float gc[GROUP_SIZE];
    #pragma unroll
    for (int bb = 0; bb < GROUP_SIZE; ++bb) gc[bb] = expw(__ldcg(&g_pm[b0 + bb]), gm);

    #pragma unroll
    for (int r = 0; r < 2; ++r) {
        const int d = tid + r * MAIN_THREADS;
        float acc = 0.f;
        #pragma unroll
        for (int bb = 0; bb < GROUP_SIZE; ++bb)
            acc += gc[bb] * __ldcg(&g_pacc[(size_t)(b0 + bb) * KD + d]);
        g_gacc[grp * KD + d] = acc;
    }
    if (tid == 0) {
        float gl = 0.f;
        #pragma unroll
        for (int bb = 0; bb < GROUP_SIZE; ++bb) gl += gc[bb] * __ldcg(&g_pl[b0 + bb]);
        g_gm[grp] = gm;
        g_gl[grp] = gl;
    }
}

// ---------------- Kernel 3: single-block finalize over 37 group partials ----------------
__global__ __launch_bounds__(KD)
void reduce_out(float* __restrict__ out) {
    __shared__ float s_gm[NGROUPS];
    __shared__ float s_gl[NGROUPS];
    const int t = threadIdx.x;                 // 512 threads, one dim each
    if (t < NGROUPS) { s_gm[t] = g_gm[t]; s_gl[t] = g_gl[t]; }
    __syncthreads();

    // every thread redundantly computes M and L (37-long loops, trivially cheap)
    float M = neg_inf();
    #pragma unroll
    for (int g = 0; g < NGROUPS; ++g) M = fmaxf(M, s_gm[g]);
    float L = 0.f;
    float acc = 0.f;
    #pragma unroll
    for (int g = 0; g < NGROUPS; ++g) {
        const float cg = expw(s_gm[g], M);
        L += cg * s_gl[g];
        acc += cg * g_gacc[g * KD + t];
    }
    out[t] = acc / L;
}

extern "C" void kernel_launch(void* const* d_in, const int* in_sizes, int n_in,
                              void* d_out, int out_size) {
    const float* query = (const float*)d_in[0];
    const float* key   = (const float*)d_in[1];
    const float* value = (const float*)d_in[2];
    const float* W     = (const float*)d_in[3];
    const float* b     = (const float*)d_in[4];
    float* out = (float*)d_out;

    qproj_kernel<<<128, 128>>>(query, W, b);
    attn_main<<<MAIN_BLOCKS, MAIN_THREADS>>>(key, value);
    reduce_out<<<1, KD>>>(out);
}

// round 13
// speedup vs baseline: 1.6100x; 1.5330x over previous
#include <cuda_runtime.h>

#define KD 512
#define QD 256
#define N_ROWS 262144

#define MAIN_BLOCKS 444
#define MAIN_THREADS 256
#define WARPS_PER_BLOCK (MAIN_THREADS / 32)
#define CHUNK 16
#define NGROUPS 37
#define GROUP_SIZE (MAIN_BLOCKS / NGROUPS)      // 12
#define SKIP_MARGIN 30.0f

// Scratch (static __device__ — no allocations allowed)
__device__ __align__(16) float g_q[KD];
__device__ float g_pm[MAIN_BLOCKS];
__device__ float g_pl[MAIN_BLOCKS];
__device__ __align__(16) float g_pacc[(size_t)MAIN_BLOCKS * KD];  // 0.91 MB
__device__ float g_gm[NGROUPS];
__device__ float g_gl[NGROUPS];
__device__ __align__(16) float g_gacc[NGROUPS * KD];              // 76 KB
__device__ unsigned g_row_ctr;
__device__ unsigned g_gdone[NGROUPS];
__device__ unsigned g_smax;            // float-ordered encoding of global running max score

__device__ __forceinline__ float neg_inf() { return __int_as_float(0xff800000); }

// safe exp(a - b): returns 0 when a == -inf (avoids -inf - -inf = NaN)
__device__ __forceinline__ float expw(float a, float b) {
    return (a == neg_inf()) ? 0.f : __expf(a - b);
}

// order-preserving float <-> uint encoding (for atomicMax on floats incl. negatives)
__device__ __forceinline__ unsigned enc_f(float x) {
    unsigned u = __float_as_uint(x);
    return (u & 0x80000000u) ? ~u : (u | 0x80000000u);
}
__device__ __forceinline__ float dec_f(unsigned e) {
    unsigned u = (e & 0x80000000u) ? (e ^ 0x80000000u) : ~e;
    return __uint_as_float(u);
}
#define SMAX_INIT 0x007FFFFFu   // enc_f(-inf)

// ---------------- Kernel 1: q = W @ query + b (128 blocks x 4 warps) + counter resets ----------------
__global__ __launch_bounds__(128)
void qproj_kernel(const float* __restrict__ query,
                  const float* __restrict__ W,
                  const float* __restrict__ b) {
    if (blockIdx.x == 0) {
        if (threadIdx.x == 0) { g_row_ctr = 0u; g_smax = SMAX_INIT; }
        if (threadIdx.x < NGROUPS) g_gdone[threadIdx.x] = 0u;
    }
    const int wid  = threadIdx.x >> 5;
    const int lane = threadIdx.x & 31;
    const int row  = blockIdx.x * 4 + wid;      // 128*4 = 512 rows

    const float4* w4 = reinterpret_cast<const float4*>(W + (size_t)row * QD);
    const float4* q4 = reinterpret_cast<const float4*>(query);
    const float4 wa = __ldg(&w4[lane]);
    const float4 wb = __ldg(&w4[lane + 32]);
    const float4 qa = __ldg(&q4[lane]);
    const float4 qb = __ldg(&q4[lane + 32]);

    float s = wa.x * qa.x + wa.y * qa.y + wa.z * qa.z + wa.w * qa.w
            + wb.x * qb.x + wb.y * qb.y + wb.z * qb.z + wb.w * qb.w;
    #pragma unroll
    for (int o = 16; o > 0; o >>= 1) s += __shfl_xor_sync(0xffffffffu, s, o);
    if (lane == 0) g_q[row] = s + b[row];
}

// ---------------- Kernel 2: streaming pass with score-gated v loads + overlapped group pre-reduce ----------------
__global__ __launch_bounds__(MAIN_THREADS, 3)
void attn_main(const float* __restrict__ key, const float* __restrict__ value) {
    __shared__ float s_m[WARPS_PER_BLOCK];
    __shared__ float s_l[WARPS_PER_BLOCK];
    __shared__ __align__(16) float s_acc[WARPS_PER_BLOCK][KD];   // 16 KB
    __shared__ int s_last;

    const int lane = threadIdx.x & 31;
    const int wid  = threadIdx.x >> 5;
    const int tid  = threadIdx.x;

    const float4* q4 = reinterpret_cast<const float4*>(g_q);
    const float4 q0 = q4[lane], q1 = q4[lane + 32], q2 = q4[lane + 64], q3 = q4[lane + 96];

    const float4* __restrict__ k4 = reinterpret_cast<const float4*>(key);
    const float4* __restrict__ v4 = reinterpret_cast<const float4*>(value);

    float4 a0 = make_float4(0.f, 0.f, 0.f, 0.f), a1 = a0, a2 = a0, a3 = a0;
    float m = neg_inf();
    float l = 0.f;
    float gm = neg_inf();   // best-known global max score (conservative lower bound)

    // dynamic chunk grabbing with one-chunk lookahead
    unsigned cur = 0u;
    if (lane == 0) cur = atomicAdd(&g_row_ctr, (unsigned)CHUNK);
    cur = __shfl_sync(0xffffffffu, cur, 0);

    while (cur < (unsigned)N_ROWS) {
        unsigned nxt = 0u;
        float gm_new = gm;
        if (lane == 0) {
            nxt = atomicAdd(&g_row_ctr, (unsigned)CHUNK);       // issued early, latency hidden
            const unsigned old = atomicMax(&g_smax, enc_f(m));  // publish local max, read global
            gm_new = dec_f(old);
        }
        nxt = __shfl_sync(0xffffffffu, nxt, 0);
        gm = fmaxf(gm, __shfl_sync(0xffffffffu, gm_new, 0));

        // rows with s <= thresh contribute < e^-SKIP_MARGIN relative weight -> skip v entirely
        float thresh = fmaxf(m, gm) - SKIP_MARGIN;

        const unsigned row_end = min(cur + (unsigned)CHUNK, (unsigned)N_ROWS);
        for (unsigned row = cur; row < row_end; ++row) {
            const size_t base = (size_t)row * (KD / 4) + lane;
            const float4 k0 = __ldcs(&k4[base]);
            const float4 k1 = __ldcs(&k4[base + 32]);
            const float4 k2 = __ldcs(&k4[base + 64]);
            const float4 k3 = __ldcs(&k4[base + 96]);

            float s;
            s  = k0.x * q0.x + k0.y * q0.y + k0.z * q0.z + k0.w * q0.w;
            s += k1.x * q1.x + k1.y * q1.y + k1.z * q1.z + k1.w * q1.w;
            s += k2.x * q2.x + k2.y * q2.y + k2.z * q2.z + k2.w * q2.w;
            s += k3.x * q3.x + k3.y * q3.y + k3.z * q3.z + k3.w * q3.w;
            #pragma unroll
            for (int o = 16; o > 0; o >>= 1) s += __shfl_xor_sync(0xffffffffu, s, o);

            if (s > thresh) {                       // warp-uniform branch
                const float4 v0 = __ldcs(&v4[base]);
                const float4 v1 = __ldcs(&v4[base + 32]);
                const float4 v2 = __ldcs(&v4[base + 64]);
                const float4 v3 = __ldcs(&v4[base + 96]);

                if (s > m) {
                    const float sc = (m == neg_inf()) ? 0.f : __expf(m - s);
                    m = s;
                    thresh = fmaxf(m, gm) - SKIP_MARGIN;
                    l = l * sc + 1.f;
                    a0.x = a0.x * sc + v0.x;  a0.y = a0.y * sc + v0.y;
                    a0.z = a0.z * sc + v0.z;  a0.w = a0.w * sc + v0.w;
                    a1.x = a1.x * sc + v1.x;  a1.y = a1.y * sc + v1.y;
                    a1.z = a1.z * sc + v1.z;  a1.w = a1.w * sc + v1.w;
                    a2.x = a2.x * sc + v2.x;  a2.y = a2.y * sc + v2.y;
                    a2.z = a2.z * sc + v2.z;  a2.w = a2.w * sc + v2.w;
                    a3.x = a3.x * sc + v3.x;  a3.y = a3.y * sc + v3.y;
                    a3.z = a3.z * sc + v3.z;  a3.w = a3.w * sc + v3.w;
                } else {
                    const float w = __expf(s - m);
                    l += w;
                    a0.x += w * v0.x;  a0.y += w * v0.y;  a0.z += w * v0.z;  a0.w += w * v0.w;
                    a1.x += w * v1.x;  a1.y += w * v1.y;  a1.z += w * v1.z;  a1.w += w * v1.w;
                    a2.x += w * v2.x;  a2.y += w * v2.y;  a2.z += w * v2.z;  a2.w += w * v2.w;
                    a3.x += w * v3.x;  a3.y += w * v3.y;  a3.z += w * v3.z;  a3.w += w * v3.w;
                }
            }
        }
        cur = nxt;
    }

    // ---- block-level reduce of 8 warp partials ----
    float4* sa = reinterpret_cast<float4*>(s_acc[wid]);
    sa[lane] = a0; sa[lane + 32] = a1; sa[lane + 64] = a2; sa[lane + 96] = a3;
    if (lane == 0) { s_m[wid] = m; s_l[wid] = l; }
    __syncthreads();

    float Mb = neg_inf();
    #pragma unroll
    for (int w = 0; w < WARPS_PER_BLOCK; ++w) Mb = fmaxf(Mb, s_m[w]);
    float c[WARPS_PER_BLOCK];
    #pragma unroll
    for (int w = 0; w < WARPS_PER_BLOCK; ++w) c[w] = expw(s_m[w], Mb);

    #pragma unroll
    for (int r = 0; r < 2; ++r) {
        const int d = tid + r * MAIN_THREADS;
        float acc = 0.f;
        #pragma unroll
        for (int w = 0; w < WARPS_PER_BLOCK; ++w) acc += c[w] * s_acc[w][d];
        g_pacc[(size_t)blockIdx.x * KD + d] = acc;
    }
    if (tid == 0) {
        float lb = 0.f;
        #pragma unroll
        for (int w = 0; w < WARPS_PER_BLOCK; ++w) lb += c[w] * s_l[w];
        g_pm[blockIdx.x] = Mb;
        g_pl[blockIdx.x] = lb;
    }
    __syncthreads();

    // ---- group ticket: last finisher of each 12-block group pre-reduces (overlaps stream) ----
    const int grp = blockIdx.x / GROUP_SIZE;
    if (tid == 0) {
        __threadfence();
        const unsigned d = atomicAdd(&g_gdone[grp], 1u);
        s_last = (d == GROUP_SIZE - 1u) ? 1 : 0;
    }
    __syncthreads();
    if (!s_last) return;

    const int b0 = grp * GROUP_SIZE;
    float gmx = neg_inf();
    #pragma unroll
    for (int bb = 0; bb < GROUP_SIZE; ++bb) gmx = fmaxf(gmx, __ldcg(&g_pm[b0 + bb]));
    float gc[GROUP_SIZE];
    #pragma unroll
    for (int bb = 0; bb < GROUP_SIZE; ++bb) gc[bb] = expw(__ldcg(&g_pm[b0 + bb]), gmx);

    #pragma unroll
    for (int r = 0; r < 2; ++r) {
        const int d = tid + r * MAIN_THREADS;
        float acc = 0.f;
        #pragma unroll
        for (int bb = 0; bb < GROUP_SIZE; ++bb)
            acc += gc[bb] * __ldcg(&g_pacc[(size_t)(b0 + bb) * KD + d]);
        g_gacc[grp * KD + d] = acc;
    }
    if (tid == 0) {
        float gl = 0.f;
        #pragma unroll
        for (int bb = 0; bb < GROUP_SIZE; ++bb) gl += gc[bb] * __ldcg(&g_pl[b0 + bb]);
        g_gm[grp] = gmx;
        g_gl[grp] = gl;
    }
}

// ---------------- Kernel 3: single-block finalize over 37 group partials ----------------
__global__ __launch_bounds__(KD)
void reduce_out(float* __restrict__ out) {
    __shared__ float s_gm[NGROUPS];
    __shared__ float s_gl[NGROUPS];
    const int t = threadIdx.x;                 // 512 threads, one dim each
    if (t < NGROUPS) { s_gm[t] = g_gm[t]; s_gl[t] = g_gl[t]; }
    __syncthreads();

    float M = neg_inf();
    #pragma unroll
    for (int g = 0; g < NGROUPS; ++g) M = fmaxf(M, s_gm[g]);
    float L = 0.f;
    float acc = 0.f;
    #pragma unroll
    for (int g = 0; g < NGROUPS; ++g) {
        const float cg = expw(s_gm[g], M);
        L += cg * s_gl[g];
        acc += cg * g_gacc[g * KD + t];
    }
    out[t] = acc / L;
}

extern "C" void kernel_launch(void* const* d_in, const int* in_sizes, int n_in,
                              void* d_out, int out_size) {
    const float* query = (const float*)d_in[0];
    const float* key   = (const float*)d_in[1];
    const float* value = (const float*)d_in[2];
    const float* W     = (const float*)d_in[3];
    const float* b     = (const float*)d_in[4];
    float* out = (float*)d_out;

    qproj_kernel<<<128, 128>>>(query, W, b);
    attn_main<<<MAIN_BLOCKS, MAIN_THREADS>>>(key, value);
    reduce_out<<<1, KD>>>(out);
}

// round 14
// speedup vs baseline: 1.7700x; 1.0994x over previous
#include <cuda_runtime.h>

#define KD 512
#define QD 256
#define N_ROWS 262144

#define MAIN_BLOCKS 444
#define MAIN_THREADS 256
#define WARPS_PER_BLOCK (MAIN_THREADS / 32)
#define CHUNK 16
#define NGROUPS 37
#define GROUP_SIZE (MAIN_BLOCKS / NGROUPS)      // 12
#define SKIP_MARGIN 30.0f

// Scratch (static __device__ — no allocations allowed)
__device__ __align__(16) float g_q[KD];
__device__ float g_pm[MAIN_BLOCKS];
__device__ float g_pl[MAIN_BLOCKS];
__device__ __align__(16) float g_pacc[(size_t)MAIN_BLOCKS * KD];  // 0.91 MB
__device__ float g_gm[NGROUPS];
__device__ float g_gl[NGROUPS];
__device__ __align__(16) float g_gacc[NGROUPS * KD];              // 76 KB
__device__ unsigned g_row_ctr;
__device__ unsigned g_gdone[NGROUPS];
__device__ unsigned g_smax;            // float-ordered encoding of global running max score

__device__ __forceinline__ float neg_inf() { return __int_as_float(0xff800000); }

// safe exp(a - b): returns 0 when a == -inf (avoids -inf - -inf = NaN)
__device__ __forceinline__ float expw(float a, float b) {
    return (a == neg_inf()) ? 0.f : __expf(a - b);
}

// order-preserving float <-> uint encoding (for atomicMax on floats incl. negatives)
__device__ __forceinline__ unsigned enc_f(float x) {
    unsigned u = __float_as_uint(x);
    return (u & 0x80000000u) ? ~u : (u | 0x80000000u);
}
__device__ __forceinline__ float dec_f(unsigned e) {
    unsigned u = (e & 0x80000000u) ? (e ^ 0x80000000u) : ~e;
    return __uint_as_float(u);
}
#define SMAX_INIT 0x007FFFFFu   // enc_f(-inf)

// ---------------- Kernel 1: q = W @ query + b (128 blocks x 4 warps) + counter resets ----------------
__global__ __launch_bounds__(128)
void qproj_kernel(const float* __restrict__ query,
                  const float* __restrict__ W,
                  const float* __restrict__ b) {
    if (blockIdx.x == 0) {
        if (threadIdx.x == 0) { g_row_ctr = 0u; g_smax = SMAX_INIT; }
        if (threadIdx.x < NGROUPS) g_gdone[threadIdx.x] = 0u;
    }
    const int wid  = threadIdx.x >> 5;
    const int lane = threadIdx.x & 31;
    const int row  = blockIdx.x * 4 + wid;      // 128*4 = 512 rows

    const float4* w4 = reinterpret_cast<const float4*>(W + (size_t)row * QD);
    const float4* q4 = reinterpret_cast<const float4*>(query);
    const float4 wa = __ldg(&w4[lane]);
    const float4 wb = __ldg(&w4[lane + 32]);
    const float4 qa = __ldg(&q4[lane]);
    const float4 qb = __ldg(&q4[lane + 32]);

    float s = wa.x * qa.x + wa.y * qa.y + wa.z * qa.z + wa.w * qa.w
            + wb.x * qb.x + wb.y * qb.y + wb.z * qb.z + wb.w * qb.w;
    #pragma unroll
    for (int o = 16; o > 0; o >>= 1) s += __shfl_xor_sync(0xffffffffu, s, o);
    if (lane == 0) g_q[row] = s + b[row];
}

// ---------------- Kernel 2: streaming pass, two-phase first chunk, gated v loads ----------------
__global__ __launch_bounds__(MAIN_THREADS, 3)
void attn_main(const float* __restrict__ key, const float* __restrict__ value) {
    __shared__ float s_m[WARPS_PER_BLOCK];
    __shared__ float s_l[WARPS_PER_BLOCK];
    __shared__ __align__(16) float s_acc[WARPS_PER_BLOCK][KD];   // 16 KB
    __shared__ float s_sc[WARPS_PER_BLOCK][CHUNK];               // 512 B: first-chunk scores
    __shared__ int s_last;

    const int lane = threadIdx.x & 31;
    const int wid  = threadIdx.x >> 5;
    const int tid  = threadIdx.x;

    const float4* q4 = reinterpret_cast<const float4*>(g_q);
    const float4 q0 = q4[lane], q1 = q4[lane + 32], q2 = q4[lane + 64], q3 = q4[lane + 96];

    const float4* __restrict__ k4 = reinterpret_cast<const float4*>(key);
    const float4* __restrict__ v4 = reinterpret_cast<const float4*>(value);

    float4 a0 = make_float4(0.f, 0.f, 0.f, 0.f), a1 = a0, a2 = a0, a3 = a0;
    float m = neg_inf();
    float l = 0.f;
    float gm = neg_inf();   // best-known global max score (conservative lower bound)

    // ======== first chunk: phase A (score-only; full 16 rows guaranteed: 3552*16 < N) ========
    unsigned cur = 0u;
    if (lane == 0) cur = atomicAdd(&g_row_ctr, (unsigned)CHUNK);
    cur = __shfl_sync(0xffffffffu, cur, 0);

    {
        #pragma unroll 4
        for (int i = 0; i < CHUNK; ++i) {
            const size_t base = (size_t)(cur + i) * (KD / 4) + lane;
            const float4 k0 = __ldcs(&k4[base]);
            const float4 k1 = __ldcs(&k4[base + 32]);
            const float4 k2 = __ldcs(&k4[base + 64]);
            const float4 k3 = __ldcs(&k4[base + 96]);
            float s;
            s  = k0.x * q0.x + k0.y * q0.y + k0.z * q0.z + k0.w * q0.w;
            s += k1.x * q1.x + k1.y * q1.y + k1.z * q1.z + k1.w * q1.w;
            s += k2.x * q2.x + k2.y * q2.y + k2.z * q2.z + k2.w * q2.w;
            s += k3.x * q3.x + k3.y * q3.y + k3.z * q3.z + k3.w * q3.w;
            #pragma unroll
            for (int o = 16; o > 0; o >>= 1) s += __shfl_xor_sync(0xffffffffu, s, o);
            if (lane == 0) s_sc[wid][i] = s;
            m = fmaxf(m, s);
        }
        __syncwarp();

        // publish local max, learn global max (most warps arrive ~simultaneously -> good gm)
        float gm_new = gm;
        if (lane == 0) gm_new = dec_f(atomicMax(&g_smax, enc_f(m)));
        gm = fmaxf(gm, __shfl_sync(0xffffffffu, gm_new, 0));

        // phase B: gated v gather for the first chunk
        const float thr = fmaxf(m, gm) - SKIP_MARGIN;
        #pragma unroll 4
        for (int i = 0; i < CHUNK; ++i) {
            const float s = s_sc[wid][i];
            if (s > thr) {
                const size_t base = (size_t)(cur + i) * (KD / 4) + lane;
                const float4 v0 = __ldcs(&v4[base]);
                const float4 v1 = __ldcs(&v4[base + 32]);
                const float4 v2 = __ldcs(&v4[base + 64]);
                const float4 v3 = __ldcs(&v4[base + 96]);
                const float w = __expf(s - m);
                l += w;
                a0.x += w * v0.x;  a0.y += w * v0.y;  a0.z += w * v0.z;  a0.w += w * v0.w;
                a1.x += w * v1.x;  a1.y += w * v1.y;  a1.z += w * v1.z;  a1.w += w * v1.w;
                a2.x += w * v2.x;  a2.y += w * v2.y;  a2.z += w * v2.z;  a2.w += w * v2.w;
                a3.x += w * v3.x;  a3.y += w * v3.y;  a3.z += w * v3.z;  a3.w += w * v3.w;
            }
        }
    }

    // grab next chunk and enter steady-state loop
    if (lane == 0) cur = atomicAdd(&g_row_ctr, (unsigned)CHUNK);
    cur = __shfl_sync(0xffffffffu, cur, 0);

    while (cur < (unsigned)N_ROWS) {
        unsigned nxt = 0u;
        float gm_new = gm;
        if (lane == 0) {
            nxt = atomicAdd(&g_row_ctr, (unsigned)CHUNK);       // issued early, latency hidden
            gm_new = dec_f(atomicMax(&g_smax, enc_f(m)));       // publish local max, read global
        }
        nxt = __shfl_sync(0xffffffffu, nxt, 0);
        gm = fmaxf(gm, __shfl_sync(0xffffffffu, gm_new, 0));

        float thresh = fmaxf(m, gm) - SKIP_MARGIN;

        const unsigned row_end = min(cur + (unsigned)CHUNK, (unsigned)N_ROWS);
        for (unsigned row = cur; row < row_end; ++row) {
            const size_t base = (size_t)row * (KD / 4) + lane;
            const float4 k0 = __ldcs(&k4[base]);
            const float4 k1 = __ldcs(&k4[base + 32]);
            const float4 k2 = __ldcs(&k4[base + 64]);
            const float4 k3 = __ldcs(&k4[base + 96]);

            float s;
            s  = k0.x * q0.x + k0.y * q0.y + k0.z * q0.z + k0.w * q0.w;
            s += k1.x * q1.x + k1.y * q1.y + k1.z * q1.z + k1.w * q1.w;
            s += k2.x * q2.x + k2.y * q2.y + k2.z * q2.z + k2.w * q2.w;
            s += k3.x * q3.x + k3.y * q3.y + k3.z * q3.z + k3.w * q3.w;
            #pragma unroll
            for (int o = 16; o > 0; o >>= 1) s += __shfl_xor_sync(0xffffffffu, s, o);

            if (s > thresh) {                       // warp-uniform branch
                const float4 v0 = __ldcs(&v4[base]);
                const float4 v1 = __ldcs(&v4[base + 32]);
                const float4 v2 = __ldcs(&v4[base + 64]);
                const float4 v3 = __ldcs(&v4[base + 96]);

                if (s > m) {
                    const float sc = (m == neg_inf()) ? 0.f : __expf(m - s);
                    m = s;
                    thresh = fmaxf(m, gm) - SKIP_MARGIN;
                    l = l * sc + 1.f;
                    a0.x = a0.x * sc + v0.x;  a0.y = a0.y * sc + v0.y;
                    a0.z = a0.z * sc + v0.z;  a0.w = a0.w * sc + v0.w;
                    a1.x = a1.x * sc + v1.x;  a1.y = a1.y * sc + v1.y;
                    a1.z = a1.z * sc + v1.z;  a1.w = a1.w * sc + v1.w;
                    a2.x = a2.x * sc + v2.x;  a2.y = a2.y * sc + v2.y;
                    a2.z = a2.z * sc + v2.z;  a2.w = a2.w * sc + v2.w;
                    a3.x = a3.x * sc + v3.x;  a3.y = a3.y * sc + v3.y;
                    a3.z = a3.z * sc + v3.z;  a3.w = a3.w * sc + v3.w;
                } else {
                    const float w = __expf(s - m);
                    l += w;
                    a0.x += w * v0.x;  a0.y += w * v0.y;  a0.z += w * v0.z;  a0.w += w * v0.w;
                    a1.x += w * v1.x;  a1.y += w * v1.y;  a1.z += w * v1.z;  a1.w += w * v1.w;
                    a2.x += w * v2.x;  a2.y += w * v2.y;  a2.z += w * v2.z;  a2.w += w * v2.w;
                    a3.x += w * v3.x;  a3.y += w * v3.y;  a3.z += w * v3.z;  a3.w += w * v3.w;
                }
            }
        }
        cur = nxt;
    }

    // ---- block-level reduce of 8 warp partials ----
    float4* sa = reinterpret_cast<float4*>(s_acc[wid]);
    sa[lane] = a0; sa[lane + 32] = a1; sa[lane + 64] = a2; sa[lane + 96] = a3;
    if (lane == 0) { s_m[wid] = m; s_l[wid] = l; }
    __syncthreads();

    float Mb = neg_inf();
    #pragma unroll
    for (int w = 0; w < WARPS_PER_BLOCK; ++w) Mb = fmaxf(Mb, s_m[w]);
    float c[WARPS_PER_BLOCK];
    #pragma unroll
    for (int w = 0; w < WARPS_PER_BLOCK; ++w) c[w] = expw(s_m[w], Mb);

    #pragma unroll
    for (int r = 0; r < 2; ++r) {
        const int d = tid + r * MAIN_THREADS;
        float acc = 0.f;
        #pragma unroll
        for (int w = 0; w < WARPS_PER_BLOCK; ++w) acc += c[w] * s_acc[w][d];
        g_pacc[(size_t)blockIdx.x * KD + d] = acc;
    }
    if (tid == 0) {
        float lb = 0.f;
        #pragma unroll
        for (int w = 0; w < WARPS_PER_BLOCK; ++w) lb += c[w] * s_l[w];
        g_pm[blockIdx.x] = Mb;
        g_pl[blockIdx.x] = lb;
    }
    __syncthreads();

    // ---- group ticket: last finisher of each 12-block group pre-reduces (overlaps stream) ----
    const int grp = blockIdx.x / GROUP_SIZE;
    if (tid == 0) {
        __threadfence();
        const unsigned d = atomicAdd(&g_gdone[grp], 1u);
        s_last = (d == GROUP_SIZE - 1u) ? 1 : 0;
    }
    __syncthreads();
    if (!s_last) return;

    const int b0 = grp * GROUP_SIZE;
    float gmx = neg_inf();
    #pragma unroll
    for (int bb = 0; bb < GROUP_SIZE; ++bb) gmx = fmaxf(gmx, __ldcg(&g_pm[b0 + bb]));
    float gc[GROUP_SIZE];
    #pragma unroll
    for (int bb = 0; bb < GROUP_SIZE; ++bb) gc[bb] = expw(__ldcg(&g_pm[b0 + bb]), gmx);

    #pragma unroll
    for (int r = 0; r < 2; ++r) {
        const int d = tid + r * MAIN_THREADS;
        float acc = 0.f;
        #pragma unroll
        for (int bb = 0; bb < GROUP_SIZE; ++bb)
            acc += gc[bb] * __ldcg(&g_pacc[(size_t)(b0 + bb) * KD + d]);
        g_gacc[grp * KD + d] = acc;
    }
    if (tid == 0) {
        float gl = 0.f;
        #pragma unroll
        for (int bb = 0; bb < GROUP_SIZE; ++bb) gl += gc[bb] * __ldcg(&g_pl[b0 + bb]);
        g_gm[grp] = gmx;
        g_gl[grp] = gl;
    }
}

// ---------------- Kernel 3: single-block finalize over 37 group partials ----------------
__global__ __launch_bounds__(KD)
void reduce_out(float* __restrict__ out) {
    __shared__ float s_gm[NGROUPS];
    __shared__ float s_gl[NGROUPS];
    const int t = threadIdx.x;                 // 512 threads, one dim each
    if (t < NGROUPS) { s_gm[t] = g_gm[t]; s_gl[t] = g_gl[t]; }
    __syncthreads();

    float M = neg_inf();
    #pragma unroll
    for (int g = 0; g < NGROUPS; ++g) M = fmaxf(M, s_gm[g]);
    float L = 0.f;
    float acc = 0.f;
    #pragma unroll
    for (int g = 0; g < NGROUPS; ++g) {
        const float cg = expw(s_gm[g], M);
        L += cg * s_gl[g];
        acc += cg * g_gacc[g * KD + t];
    }
    out[t] = acc / L;
}

extern "C" void kernel_launch(void* const* d_in, const int* in_sizes, int n_in,
                              void* d_out, int out_size) {
    const float* query = (const float*)d_in[0];
    const float* key   = (const float*)d_in[1];
    const float* value = (const float*)d_in[2];
    const float* W     = (const float*)d_in[3];
    const float* b     = (const float*)d_in[4];
    float* out = (float*)d_out;

    qproj_kernel<<<128, 128>>>(query, W, b);
    attn_main<<<MAIN_BLOCKS, MAIN_THREADS>>>(key, value);
    reduce_out<<<1, KD>>>(out);
}